// round 15
// baseline (speedup 1.0000x reference)
#include <cuda_runtime.h>
#include <cuda_fp16.h>
#include <math.h>
#include <stdint.h>

#define C_FULL 1024
#define C_HALF 512
#define HW     4096
#define KLOG   2048

// ---------------- scratch (device globals; no runtime allocation) ----------
__device__ __half g_xm_h[C_FULL*HW], g_xm_l[C_FULL*HW];   // x splits, native [C,HW]
__device__ __half g_xf_h[C_FULL*HW], g_xf_l[C_FULL*HW];
__device__ __half g_xl_h[C_FULL*HW], g_xl_l[C_FULL*HW];
__device__ __half g_Wq_h [C_HALF*C_FULL], g_Wq_l [C_HALF*C_FULL];
__device__ __half g_Wk1_h[C_HALF*C_FULL], g_Wk1_l[C_HALF*C_FULL];
__device__ __half g_Wk2_h[C_HALF*C_FULL], g_Wk2_l[C_HALF*C_FULL];
__device__ __half g_Wv_h [C_FULL*C_FULL];                 // lo of Wv unused
__device__ __half g_q_h [C_HALF*HW], g_q_l [C_HALF*HW];
__device__ __half g_kf_h[C_HALF*HW], g_kf_l[C_HALF*HW];
__device__ __half g_kl_h[C_HALF*HW], g_kl_l[C_HALF*HW];
__device__ __half g_v_h[C_FULL*HW];                       // v, native [C,HW]
__device__ float  g_lf0[C_FULL*C_FULL], g_lf1[C_FULL*C_FULL];
__device__ float  g_ll0[C_FULL*C_FULL], g_ll1[C_FULL*C_FULL];
__device__ __half g_S_h[C_FULL*C_FULL];                   // 1-term final

// ---------------- helpers ---------------------------------------------------
__device__ __forceinline__ uint32_t smem_u32(const void* p) {
    uint32_t r;
    asm("{ .reg .u64 t; cvta.to.shared.u64 t, %1; cvt.u32.u64 %0, t; }"
        : "=r"(r) : "l"(p));
    return r;
}
__device__ __forceinline__ void cp_async16(uint32_t dst, const void* src) {
    asm volatile("cp.async.cg.shared.global [%0], [%1], 16;" :: "r"(dst), "l"(src));
}
__device__ __forceinline__ void cp_commit() { asm volatile("cp.async.commit_group;"); }

__device__ __forceinline__ void ldsm4(uint32_t addr, uint32_t& r0, uint32_t& r1,
                                      uint32_t& r2, uint32_t& r3) {
    asm volatile("ldmatrix.sync.aligned.m8n8.x4.shared.b16 {%0,%1,%2,%3}, [%4];"
                 : "=r"(r0), "=r"(r1), "=r"(r2), "=r"(r3) : "r"(addr));
}
__device__ __forceinline__ void ldsm4_t(uint32_t addr, uint32_t& r0, uint32_t& r1,
                                        uint32_t& r2, uint32_t& r3) {
    asm volatile("ldmatrix.sync.aligned.m8n8.x4.trans.shared.b16 {%0,%1,%2,%3}, [%4];"
                 : "=r"(r0), "=r"(r1), "=r"(r2), "=r"(r3) : "r"(addr));
}
__device__ __forceinline__ void hmma(float* d, const uint32_t* a,
                                     uint32_t b0, uint32_t b1) {
    asm volatile("mma.sync.aligned.m16n8k16.row.col.f32.f16.f16.f32 "
                 "{%0,%1,%2,%3}, {%4,%5,%6,%7}, {%8,%9}, {%0,%1,%2,%3};"
                 : "+f"(d[0]), "+f"(d[1]), "+f"(d[2]), "+f"(d[3])
                 : "r"(a[0]), "r"(a[1]), "r"(a[2]), "r"(a[3]),
                   "r"(b0), "r"(b1));
}

// ---------------- unified multi-job GEMM (templated core) -------------------
// TRB_=0: D = A[M,K'] @ B[N,K']^T ; TRB_=1: D = A[M,K'] @ B[K',N]
// tm bit0: + A_h*B_l; bit1: + A_l*B_h (A_h*B_h always).
// mode 0: split-store D+bias[m]; 1: hi-store D+bias[m]; 2: fp32 D;
// mode 3: fp32 gamma*D + 0.5*(xf+xl)
struct Jobs {
    const __half* Ah[4]; const __half* Al[4];
    const __half* Bh[4]; const __half* Bl[4];
    __half* Ch[4]; __half* Cl[4]; float* Cf[4];
    const float* bias[4];
    const float* xf; const float* xl; const float* gpt;
    int N[4], K[4], Kld[4], Bld[4], koff[4], gx[4], tm[4], mode[4], blk0[4];
    int njobs;
};

template<int BN_, int BK_, int NTHR_, int MINCTA_, int TRB_, int NST_>
__global__ __launch_bounds__(NTHR_, MINCTA_)
void mma_gemm(Jobs P)
{
    constexpr int TS  = BK_ + 8;
    constexpr int TSB = BN_ + 8;
    constexpr int TILE_A = 128 * TS * 2;
    constexpr int TILE_B = TRB_ ? (BK_ * TSB * 2) : (BN_ * TS * 2);
    constexpr int STAGE  = 2 * TILE_A + 2 * TILE_B;
    constexpr int KC     = BK_ / 8;
    constexpr int A_IT   = 128 * KC / NTHR_;
    constexpr int B_IT   = TRB_ ? (BK_ * BN_ / 8 / NTHR_) : (BN_ * KC / NTHR_);
    constexpr int KSN    = BK_ / 16;

    extern __shared__ __half sm[];
    int j = 0;
    #pragma unroll
    for (int t = 1; t < 4; t++)
        if (t < P.njobs && (int)blockIdx.x >= P.blk0[t]) j = t;
    const int rel = blockIdx.x - P.blk0[j];
    const int bx = rel % P.gx[j], by = rel / P.gx[j];

    const __half* __restrict__ Ah = P.Ah[j];
    const __half* __restrict__ Al = P.Al[j];
    const __half* __restrict__ Bh = P.Bh[j];
    const __half* __restrict__ Bl = P.Bl[j];
    const int N = P.N[j], K = P.K[j], Kld = P.Kld[j], Bld = P.Bld[j];
    const int koff = P.koff[j];
    const int tm = P.tm[j], mode = P.mode[j];

    const int tid  = threadIdx.x;
    const int lane = tid & 31, wid = tid >> 5;
    const int warp_m = wid & 3, warp_n = wid >> 2;       // warp tile 32x64
    const int bm0 = by * 128, bn0 = bx * BN_;
    const uint32_t su = smem_u32(sm);

    float acc[2][8][4];
    #pragma unroll
    for (int i = 0; i < 2; i++)
        #pragma unroll
        for (int q = 0; q < 8; q++)
            #pragma unroll
            for (int k = 0; k < 4; k++) acc[i][q][k] = 0.0f;

#define LOAD_STAGE(s, kt) do {                                                \
    const uint32_t sbase_ = su + (uint32_t)(s) * STAGE;                       \
    const size_t col0_ = (size_t)koff + (size_t)(kt) * BK_;                   \
    _Pragma("unroll")                                                         \
    for (int it_ = 0; it_ < A_IT; it_++) {                                    \
        const int c_ = tid + it_ * NTHR_;                                     \
        const int row_ = c_ / KC;                                             \
        const int kc_ = (c_ % KC) * 8;                                        \
        const uint32_t off_ = (uint32_t)(row_ * TS + kc_) * 2;                \
        const size_t ga_ = (size_t)(bm0 + row_) * Kld + col0_ + kc_;          \
        cp_async16(sbase_ + off_, Ah + ga_);                                  \
        if (tm & 2) cp_async16(sbase_ + TILE_A + off_, Al + ga_);             \
    }                                                                         \
    if (TRB_) {                                                               \
        _Pragma("unroll")                                                     \
        for (int it_ = 0; it_ < B_IT; it_++) {                                \
            const int c_ = tid + it_ * NTHR_;                                 \
            const int row_ = c_ / (BN_ / 8);                                  \
            const int nc_ = (c_ % (BN_ / 8)) * 8;                             \
            const uint32_t off_ = (uint32_t)(row_ * TSB + nc_) * 2;           \
            const size_t gb_ = (col0_ + row_) * (size_t)Bld + bn0 + nc_;      \
            cp_async16(sbase_ + 2 * TILE_A + off_, Bh + gb_);                 \
            if (tm & 1) cp_async16(sbase_ + 2 * TILE_A + TILE_B + off_,       \
                                   Bl + gb_);                                 \
        }                                                                     \
    } else {                                                                  \
        _Pragma("unroll")                                                     \
        for (int it_ = 0; it_ < B_IT; it_++) {                                \
            const int c_ = tid + it_ * NTHR_;                                 \
            const int row_ = c_ / KC;                                         \
            const int kc_ = (c_ % KC) * 8;                                    \
            const uint32_t off_ = (uint32_t)(row_ * TS + kc_) * 2;            \
            const size_t gb_ = (size_t)(bn0 + row_) * Kld + col0_ + kc_;      \
            cp_async16(sbase_ + 2 * TILE_A + off_, Bh + gb_);                 \
            if (tm & 1) cp_async16(sbase_ + 2 * TILE_A + TILE_B + off_,       \
                                   Bl + gb_);                                 \
        }                                                                     \
    }                                                                         \
    cp_commit();                                                              \
} while (0)

    const int NT = K / BK_;
    LOAD_STAGE(0, 0);
    if (NST_ >= 3 && NT > 1) LOAD_STAGE(1, 1);

    for (int kt = 0; kt < NT; kt++) {
        if (kt + NST_ - 1 < NT) {
            LOAD_STAGE((kt + NST_ - 1) % NST_, kt + NST_ - 1);
            asm volatile("cp.async.wait_group %0;" :: "n"(NST_ - 1) : "memory");
        } else if (NST_ >= 3 && kt + 1 < NT) {
            asm volatile("cp.async.wait_group 1;" ::: "memory");
        } else {
            asm volatile("cp.async.wait_group 0;" ::: "memory");
        }
        __syncthreads();

        const uint32_t sbase = su + (uint32_t)(kt % NST_) * STAGE;
        #pragma unroll
        for (int ks = 0; ks < KSN; ks++) {
            uint32_t ah[2][4], al[2][4];
            #pragma unroll
            for (int i = 0; i < 2; i++) {
                const int r   = warp_m * 32 + i * 16 + (lane & 15);
                const int col = ks * 16 + (lane >> 4) * 8;
                const uint32_t ad = sbase + (uint32_t)(r * TS + col) * 2;
                ldsm4(ad, ah[i][0], ah[i][1], ah[i][2], ah[i][3]);
                if (tm & 2)
                    ldsm4(ad + TILE_A, al[i][0], al[i][1], al[i][2], al[i][3]);
            }
            if (TRB_) {
                const uint32_t brow = sbase + 2 * TILE_A +
                    (uint32_t)((ks * 16 + (lane & 15)) * TSB + ((lane >> 4) << 3)) * 2;
                #pragma unroll
                for (int p = 0; p < 4; p++) {
                    const uint32_t bd = brow + (uint32_t)(warp_n * 64 + p * 16) * 2;
                    uint32_t b0, b1, b2, b3;
                    ldsm4_t(bd, b0, b1, b2, b3);
                    #pragma unroll
                    for (int i = 0; i < 2; i++) {
                        hmma(acc[i][2*p],   ah[i], b0, b1);
                        hmma(acc[i][2*p+1], ah[i], b2, b3);
                    }
                    if (tm & 2) {
                        #pragma unroll
                        for (int i = 0; i < 2; i++) {
                            hmma(acc[i][2*p],   al[i], b0, b1);
                            hmma(acc[i][2*p+1], al[i], b2, b3);
                        }
                    }
                    if (tm & 1) {
                        uint32_t c0, c1, c2, c3;
                        ldsm4_t(bd + TILE_B, c0, c1, c2, c3);
                        #pragma unroll
                        for (int i = 0; i < 2; i++) {
                            hmma(acc[i][2*p],   ah[i], c0, c1);
                            hmma(acc[i][2*p+1], ah[i], c2, c3);
                        }
                    }
                }
            } else {
                const int g  = lane >> 3, i8 = lane & 7;
                const int n0r = warp_n * 64 + ((g >> 1) << 3) + i8;
                const int bcol = ks * 16 + (g & 1) * 8;
                const uint32_t bd0 = sbase + 2 * TILE_A +
                                     (uint32_t)(n0r * TS + bcol) * 2;
                #pragma unroll
                for (int p = 0; p < 4; p++) {
                    const uint32_t bd = bd0 + (uint32_t)(p * 16 * TS * 2);
                    uint32_t b0, b1, b2, b3;
                    ldsm4(bd, b0, b1, b2, b3);
                    uint32_t c0, c1, c2, c3;
                    if (tm & 1)
                        ldsm4(bd + TILE_B, c0, c1, c2, c3);
                    #pragma unroll
                    for (int i = 0; i < 2; i++) {
                        hmma(acc[i][2*p],   ah[i], b0, b1);
                        hmma(acc[i][2*p+1], ah[i], b2, b3);
                    }
                    if (tm & 2) {
                        #pragma unroll
                        for (int i = 0; i < 2; i++) {
                            hmma(acc[i][2*p],   al[i], b0, b1);
                            hmma(acc[i][2*p+1], al[i], b2, b3);
                        }
                    }
                    if (tm & 1) {
                        #pragma unroll
                        for (int i = 0; i < 2; i++) {
                            hmma(acc[i][2*p],   ah[i], c0, c1);
                            hmma(acc[i][2*p+1], ah[i], c2, c3);
                        }
                    }
                }
            }
        }
        __syncthreads();
    }
#undef LOAD_STAGE

    // ---- epilogue ----
    const int tq = lane >> 2, tr = lane & 3;
    const float gam = (mode == 3) ? P.gpt[0] : 0.0f;
    #pragma unroll
    for (int i = 0; i < 2; i++) {
        #pragma unroll
        for (int h2 = 0; h2 < 2; h2++) {
            const int row = bm0 + warp_m * 32 + i * 16 + tq + h2 * 8;
            const float bm_ = (mode <= 1) ? P.bias[j][row] : 0.0f;
            #pragma unroll
            for (int q = 0; q < 8; q++) {
                const int col = bn0 + warp_n * 64 + q * 8 + tr * 2;
                float v0 = acc[i][q][h2 * 2 + 0];
                float v1 = acc[i][q][h2 * 2 + 1];
                const size_t idx = (size_t)row * N + col;
                if (mode == 0) {
                    v0 += bm_; v1 += bm_;
                    const __half h0 = __float2half_rn(v0);
                    const __half h1 = __float2half_rn(v1);
                    *reinterpret_cast<__half2*>(P.Ch[j] + idx) = __halves2half2(h0, h1);
                    *reinterpret_cast<__half2*>(P.Cl[j] + idx) =
                        __halves2half2(__float2half_rn(v0 - __half2float(h0)),
                                       __float2half_rn(v1 - __half2float(h1)));
                } else if (mode == 1) {
                    v0 += bm_; v1 += bm_;
                    *reinterpret_cast<__half2*>(P.Ch[j] + idx) =
                        __halves2half2(__float2half_rn(v0), __float2half_rn(v1));
                } else if (mode == 2) {
                    *reinterpret_cast<float2*>(P.Cf[j] + idx) = make_float2(v0, v1);
                } else {
                    const float2 a2 = *reinterpret_cast<const float2*>(P.xf + idx);
                    const float2 b2 = *reinterpret_cast<const float2*>(P.xl + idx);
                    *reinterpret_cast<float2*>(P.Cf[j] + idx) =
                        make_float2(gam * v0 + 0.5f * (a2.x + b2.x),
                                    gam * v1 + 0.5f * (a2.y + b2.y));
                }
            }
        }
    }
}

#define SMEM_CONV  113664   // <128,32,256,2,1,3>  (3-stage)
#define SMEM_LOGIT 221184   // <256,64,512,1,0,2>
#define SMEM_FIN   208896   // <256,64,512,1,1,2>

// ---------------- vectorized merged splits (8 elems/thread) -----------------
struct S8 { const float* x[8]; __half* h[8]; __half* l[8]; int end[8]; };
__global__ __launch_bounds__(256)
void split8_kernel(S8 S)
{
    const int i8 = (blockIdx.x * 256 + threadIdx.x) * 8;
    if (i8 >= S.end[7]) return;
    int j = 0;
    #pragma unroll
    for (int t = 1; t < 8; t++) if (i8 >= S.end[t - 1]) j = t;
    const int base = (j == 0) ? 0 : S.end[j - 1];
    const int k = i8 - base;
    const float4 v0 = *reinterpret_cast<const float4*>(S.x[j] + k);
    const float4 v1 = *reinterpret_cast<const float4*>(S.x[j] + k + 4);
    const float f[8] = {v0.x, v0.y, v0.z, v0.w, v1.x, v1.y, v1.z, v1.w};
    uint32_t ph[4], pl[4];
    #pragma unroll
    for (int t = 0; t < 4; t++) {
        const __half ha = __float2half_rn(f[2*t]), hb = __float2half_rn(f[2*t+1]);
        const __half2 hp = __halves2half2(ha, hb);
        ph[t] = *reinterpret_cast<const uint32_t*>(&hp);
        const __half2 lp = __halves2half2(
            __float2half_rn(f[2*t]   - __half2float(ha)),
            __float2half_rn(f[2*t+1] - __half2float(hb)));
        pl[t] = *reinterpret_cast<const uint32_t*>(&lp);
    }
    *reinterpret_cast<uint4*>(S.h[j] + k) = make_uint4(ph[0], ph[1], ph[2], ph[3]);
    if (S.l[j])
        *reinterpret_cast<uint4*>(S.l[j] + k) = make_uint4(pl[0], pl[1], pl[2], pl[3]);
}

// ---------------- fused dual softmax (shuffle reductions) -------------------
__device__ __forceinline__ float blk_red(float v, bool mx, float* red,
                                         int tid)
{
    #pragma unroll
    for (int o = 16; o > 0; o >>= 1) {
        const float t = __shfl_xor_sync(0xFFFFFFFFu, v, o);
        v = mx ? fmaxf(v, t) : (v + t);
    }
    if ((tid & 31) == 0) red[tid >> 5] = v;
    __syncthreads();
    float r = red[0];
    #pragma unroll
    for (int w = 1; w < 8; w++) r = mx ? fmaxf(r, red[w]) : (r + red[w]);
    __syncthreads();
    return r;
}

__global__ __launch_bounds__(256)
void softmax_sum_kernel(const float* __restrict__ LF0, const float* __restrict__ LF1,
                        const float* __restrict__ LL0, const float* __restrict__ LL1,
                        __half* __restrict__ Sh)
{
    const int row = blockIdx.x;
    const int tid = threadIdx.x;
    __shared__ float red[8];

    const size_t rb = (size_t)row * 1024 + tid * 4;
    const float4 f0 = *reinterpret_cast<const float4*>(LF0 + rb);
    const float4 f1 = *reinterpret_cast<const float4*>(LF1 + rb);
    const float4 l0 = *reinterpret_cast<const float4*>(LL0 + rb);
    const float4 l1 = *reinterpret_cast<const float4*>(LL1 + rb);
    const float vf[4] = {f0.x + f1.x, f0.y + f1.y, f0.z + f1.z, f0.w + f1.w};
    const float vl[4] = {l0.x + l1.x, l0.y + l1.y, l0.z + l1.z, l0.w + l1.w};

    const float Mf = blk_red(fmaxf(fmaxf(vf[0], vf[1]), fmaxf(vf[2], vf[3])),
                             true, red, tid);
    float ef[4], sf = 0.0f;
    #pragma unroll
    for (int k = 0; k < 4; k++) { ef[k] = expf(vf[k] - Mf); sf += ef[k]; }
    const float Sf = blk_red(sf, false, red, tid);

    const float Ml = blk_red(fmaxf(fmaxf(vl[0], vl[1]), fmaxf(vl[2], vl[3])),
                             true, red, tid);
    float el[4], sl = 0.0f;
    #pragma unroll
    for (int k = 0; k < 4; k++) { el[k] = expf(vl[k] - Ml); sl += el[k]; }
    const float Sl_ = blk_red(sl, false, red, tid);

    const float invf = 1.0f / Sf, invl = 1.0f / Sl_;
    uint32_t pk[2];
    #pragma unroll
    for (int t = 0; t < 2; t++) {
        const __half2 hp = __halves2half2(
            __float2half_rn(ef[2*t]   * invf + el[2*t]   * invl),
            __float2half_rn(ef[2*t+1] * invf + el[2*t+1] * invl));
        pk[t] = *reinterpret_cast<const uint32_t*>(&hp);
    }
    *reinterpret_cast<uint2*>(Sh + rb) = make_uint2(pk[0], pk[1]);
}

// ---------------------------------------------------------------------------
extern "C" void kernel_launch(void* const* d_in, const int* in_sizes, int n_in,
                              void* d_out, int out_size)
{
    (void)in_sizes; (void)n_in; (void)out_size;
    const float* x_f   = (const float*)d_in[0];
    const float* x_m   = (const float*)d_in[1];
    const float* x_l   = (const float*)d_in[2];
    const float* Wq    = (const float*)d_in[3];
    const float* bq    = (const float*)d_in[4];
    const float* Wk1   = (const float*)d_in[5];
    const float* bk1   = (const float*)d_in[6];
    const float* Wk2   = (const float*)d_in[7];
    const float* bk2   = (const float*)d_in[8];
    const float* Wv    = (const float*)d_in[9];
    const float* bv    = (const float*)d_in[10];
    const float* gamma = (const float*)d_in[11];
    float* out = (float*)d_out;

    __half *xm_h, *xm_l, *xf_h, *xf_l, *xl_h, *xl_l;
    __half *wq_h, *wq_l, *wk1_h, *wk1_l, *wk2_h, *wk2_l, *wv_h;
    __half *q_h, *q_l, *kf_h, *kf_l, *kl_h, *kl_l, *v_h, *s_h;
    float *lf0, *lf1, *ll0, *ll1;
    cudaGetSymbolAddress((void**)&xm_h, g_xm_h); cudaGetSymbolAddress((void**)&xm_l, g_xm_l);
    cudaGetSymbolAddress((void**)&xf_h, g_xf_h); cudaGetSymbolAddress((void**)&xf_l, g_xf_l);
    cudaGetSymbolAddress((void**)&xl_h, g_xl_h); cudaGetSymbolAddress((void**)&xl_l, g_xl_l);
    cudaGetSymbolAddress((void**)&wq_h,  g_Wq_h);  cudaGetSymbolAddress((void**)&wq_l,  g_Wq_l);
    cudaGetSymbolAddress((void**)&wk1_h, g_Wk1_h); cudaGetSymbolAddress((void**)&wk1_l, g_Wk1_l);
    cudaGetSymbolAddress((void**)&wk2_h, g_Wk2_h); cudaGetSymbolAddress((void**)&wk2_l, g_Wk2_l);
    cudaGetSymbolAddress((void**)&wv_h,  g_Wv_h);
    cudaGetSymbolAddress((void**)&q_h,  g_q_h);  cudaGetSymbolAddress((void**)&q_l,  g_q_l);
    cudaGetSymbolAddress((void**)&kf_h, g_kf_h); cudaGetSymbolAddress((void**)&kf_l, g_kf_l);
    cudaGetSymbolAddress((void**)&kl_h, g_kl_h); cudaGetSymbolAddress((void**)&kl_l, g_kl_l);
    cudaGetSymbolAddress((void**)&v_h, g_v_h);
    cudaGetSymbolAddress((void**)&s_h, g_S_h);
    cudaGetSymbolAddress((void**)&lf0, g_lf0);   cudaGetSymbolAddress((void**)&lf1, g_lf1);
    cudaGetSymbolAddress((void**)&ll0, g_ll0);   cudaGetSymbolAddress((void**)&ll1, g_ll1);

    cudaFuncSetAttribute(mma_gemm<128, 32, 256, 2, 1, 3>,
                         cudaFuncAttributeMaxDynamicSharedMemorySize, SMEM_CONV);
    cudaFuncSetAttribute(mma_gemm<256, 64, 512, 1, 0, 2>,
                         cudaFuncAttributeMaxDynamicSharedMemorySize, SMEM_LOGIT);
    cudaFuncSetAttribute(mma_gemm<256, 64, 512, 1, 1, 2>,
                         cudaFuncAttributeMaxDynamicSharedMemorySize, SMEM_FIN);

    // 1) all splits in one launch: 4 weights + 3 activations
    {
        S8 S = {};
        S.x[0] = Wq;  S.h[0] = wq_h;  S.l[0] = wq_l;
        S.x[1] = Wk1; S.h[1] = wk1_h; S.l[1] = wk1_l;
        S.x[2] = Wk2; S.h[2] = wk2_h; S.l[2] = wk2_l;
        S.x[3] = Wv;  S.h[3] = wv_h;  S.l[3] = nullptr;
        S.x[4] = x_m; S.h[4] = xm_h;  S.l[4] = xm_l;
        S.x[5] = x_f; S.h[5] = xf_h;  S.l[5] = xf_l;
        S.x[6] = x_l; S.h[6] = xl_h;  S.l[6] = xl_l;
        S.x[7] = Wq;  S.h[7] = wq_h;  S.l[7] = nullptr;
        const int nw = C_HALF * C_FULL, nx = C_FULL * HW;
        S.end[0] = nw; S.end[1] = 2 * nw; S.end[2] = 3 * nw;
        S.end[3] = 3 * nw + C_FULL * C_FULL;
        S.end[4] = S.end[3] + nx; S.end[5] = S.end[4] + nx;
        S.end[6] = S.end[5] + nx; S.end[7] = S.end[6];
        split8_kernel<<<(S.end[6] / 8 + 255) / 256, 256>>>(S);
    }

    // 2) all 4 conv GEMMs, narrow NN core, 3-stage (640 CTAs, 2/SM)
    {
        Jobs P = {};
        const __half* Ahs[3] = {wq_h, wk1_h, wk2_h};
        const __half* Als[3] = {wq_l, wk1_l, wk2_l};
        const __half* Bhs[3] = {xm_h, xf_h, xl_h};
        const __half* Bls[3] = {xm_l, xf_l, xl_l};
        __half* Chs[3] = {q_h, kf_h, kl_h};
        __half* Cls[3] = {q_l, kf_l, kl_l};
        const float* bs[3] = {bq, bk1, bk2};
        for (int t = 0; t < 3; t++) {
            P.Ah[t] = Ahs[t]; P.Al[t] = Als[t]; P.Bh[t] = Bhs[t]; P.Bl[t] = Bls[t];
            P.Ch[t] = Chs[t]; P.Cl[t] = Cls[t]; P.bias[t] = bs[t];
            P.N[t] = HW; P.K[t] = C_FULL; P.Kld[t] = C_FULL; P.Bld[t] = HW;
            P.koff[t] = 0;
            P.gx[t] = HW / 128;                              // 32
            P.tm[t] = 3; P.mode[t] = 0; P.blk0[t] = t * 128;
        }
        P.Ah[3] = wv_h; P.Al[3] = nullptr; P.Bh[3] = xm_h; P.Bl[3] = xm_l;
        P.Ch[3] = v_h; P.bias[3] = bv;
        P.N[3] = HW; P.K[3] = C_FULL; P.Kld[3] = C_FULL; P.Bld[3] = HW;
        P.koff[3] = 0;
        P.gx[3] = HW / 128;                                  // 32
        P.tm[3] = 1; P.mode[3] = 1; P.blk0[3] = 384;
        P.njobs = 4;
        mma_gemm<128, 32, 256, 2, 1, 3><<<640, 256, SMEM_CONV>>>(P);
    }

    // 3) logits, wide NT core, split-K=2 (4 jobs x 32 CTAs = 128)
    {
        Jobs P = {};
        const __half* As[4] = {kf_h, kf_h, kl_h, kl_h};
        const __half* Als[4] = {kf_l, kf_l, kl_l, kl_l};
        float* Cs[4] = {lf0, lf1, ll0, ll1};
        const int kos[4] = {0, 1024, 0, 1024};
        for (int t = 0; t < 4; t++) {
            P.Ah[t] = As[t]; P.Al[t] = Als[t]; P.Bh[t] = q_h; P.Bl[t] = q_l;
            P.Cf[t] = Cs[t];
            P.N[t] = C_FULL; P.K[t] = 1024; P.Kld[t] = KLOG; P.Bld[t] = KLOG;
            P.koff[t] = kos[t];
            P.gx[t] = C_FULL / 256;                          // 4
            P.tm[t] = 3; P.mode[t] = 2; P.blk0[t] = t * 32;
        }
        P.njobs = 4;
        mma_gemm<256, 64, 512, 1, 0, 2><<<128, 512, SMEM_LOGIT>>>(P);
    }

    // 4) S = softmax(lf0+lf1) + softmax(ll0+ll1)  (hi only)
    softmax_sum_kernel<<<C_FULL, 256>>>(lf0, lf1, ll0, ll1, s_h);

    // 5) out = gamma * (S_h @ v_h) + 0.5*(x_f + x_l)  (wide NN, 1-term)
    {
        Jobs P = {};
        P.Ah[0] = s_h; P.Al[0] = nullptr; P.Bh[0] = v_h; P.Bl[0] = nullptr;
        P.Cf[0] = out; P.xf = x_f; P.xl = x_l; P.gpt = gamma;
        P.N[0] = HW; P.K[0] = C_FULL; P.Kld[0] = C_FULL; P.Bld[0] = HW;
        P.koff[0] = 0;
        P.gx[0] = HW / 256;                                  // 16
        P.tm[0] = 0; P.mode[0] = 3; P.blk0[0] = 0;
        P.njobs = 1;
        mma_gemm<256, 64, 512, 1, 1, 2><<<128, 512, SMEM_FIN>>>(P);
    }
}

// round 16
// speedup vs baseline: 1.0237x; 1.0237x over previous
#include <cuda_runtime.h>
#include <cuda_fp16.h>
#include <math.h>
#include <stdint.h>

#define C_FULL 1024
#define C_HALF 512
#define HW     4096
#define KLOG   2048

// ---------------- scratch (device globals; no runtime allocation) ----------
__device__ __half g_xm_h[C_FULL*HW], g_xm_l[C_FULL*HW];   // x splits, native [C,HW]
__device__ __half g_xf_h[C_FULL*HW], g_xf_l[C_FULL*HW];
__device__ __half g_xl_h[C_FULL*HW], g_xl_l[C_FULL*HW];
__device__ __half g_Wq_h [C_HALF*C_FULL], g_Wq_l [C_HALF*C_FULL];
__device__ __half g_Wk1_h[C_HALF*C_FULL], g_Wk1_l[C_HALF*C_FULL];
__device__ __half g_Wk2_h[C_HALF*C_FULL], g_Wk2_l[C_HALF*C_FULL];
__device__ __half g_Wv_h [C_FULL*C_FULL];                 // lo of Wv unused
__device__ __half g_q_h [C_HALF*HW], g_q_l [C_HALF*HW];
__device__ __half g_kf_h[C_HALF*HW], g_kf_l[C_HALF*HW];
__device__ __half g_kl_h[C_HALF*HW], g_kl_l[C_HALF*HW];
__device__ __half g_v_h[C_FULL*HW];                       // v, native [C,HW]
__device__ float  g_lf0[C_FULL*C_FULL], g_lf1[C_FULL*C_FULL];
__device__ float  g_ll0[C_FULL*C_FULL], g_ll1[C_FULL*C_FULL];
__device__ __half g_S_h[C_FULL*C_FULL];                   // 1-term final

// ---------------- helpers ---------------------------------------------------
__device__ __forceinline__ uint32_t smem_u32(const void* p) {
    uint32_t r;
    asm("{ .reg .u64 t; cvta.to.shared.u64 t, %1; cvt.u32.u64 %0, t; }"
        : "=r"(r) : "l"(p));
    return r;
}
__device__ __forceinline__ void cp_async16(uint32_t dst, const void* src) {
    asm volatile("cp.async.cg.shared.global [%0], [%1], 16;" :: "r"(dst), "l"(src));
}
__device__ __forceinline__ void cp_commit() { asm volatile("cp.async.commit_group;"); }

__device__ __forceinline__ void ldsm4(uint32_t addr, uint32_t& r0, uint32_t& r1,
                                      uint32_t& r2, uint32_t& r3) {
    asm volatile("ldmatrix.sync.aligned.m8n8.x4.shared.b16 {%0,%1,%2,%3}, [%4];"
                 : "=r"(r0), "=r"(r1), "=r"(r2), "=r"(r3) : "r"(addr));
}
__device__ __forceinline__ void ldsm4_t(uint32_t addr, uint32_t& r0, uint32_t& r1,
                                        uint32_t& r2, uint32_t& r3) {
    asm volatile("ldmatrix.sync.aligned.m8n8.x4.trans.shared.b16 {%0,%1,%2,%3}, [%4];"
                 : "=r"(r0), "=r"(r1), "=r"(r2), "=r"(r3) : "r"(addr));
}
__device__ __forceinline__ void hmma(float* d, const uint32_t* a,
                                     uint32_t b0, uint32_t b1) {
    asm volatile("mma.sync.aligned.m16n8k16.row.col.f32.f16.f16.f32 "
                 "{%0,%1,%2,%3}, {%4,%5,%6,%7}, {%8,%9}, {%0,%1,%2,%3};"
                 : "+f"(d[0]), "+f"(d[1]), "+f"(d[2]), "+f"(d[3])
                 : "r"(a[0]), "r"(a[1]), "r"(a[2]), "r"(a[3]),
                   "r"(b0), "r"(b1));
}

// ---------------- unified multi-job GEMM (templated core) -------------------
// TRB_=0: D = A[M,K'] @ B[N,K']^T ; TRB_=1: D = A[M,K'] @ B[K',N]
// tm bit0: + A_h*B_l; bit1: + A_l*B_h (A_h*B_h always).
// mode 0: split-store D+bias[m]; 1: hi-store D+bias[m]; 2: fp32 D;
// mode 3: fp32 gamma*D + 0.5*(xf+xl)
struct Jobs {
    const __half* Ah[4]; const __half* Al[4];
    const __half* Bh[4]; const __half* Bl[4];
    __half* Ch[4]; __half* Cl[4]; float* Cf[4];
    const float* bias[4];
    const float* xf; const float* xl; const float* gpt;
    int N[4], K[4], Kld[4], Bld[4], koff[4], gx[4], tm[4], mode[4], blk0[4];
    int njobs;
};

template<int BN_, int BK_, int NTHR_, int MINCTA_, int TRB_>
__global__ __launch_bounds__(NTHR_, MINCTA_)
void mma_gemm(Jobs P)
{
    constexpr int TS  = BK_ + 8;
    constexpr int TSB = BN_ + 8;
    constexpr int TILE_A = 128 * TS * 2;
    constexpr int TILE_B = TRB_ ? (BK_ * TSB * 2) : (BN_ * TS * 2);
    constexpr int STAGE  = 2 * TILE_A + 2 * TILE_B;
    constexpr int KC     = BK_ / 8;
    constexpr int A_IT   = 128 * KC / NTHR_;
    constexpr int B_IT   = TRB_ ? (BK_ * BN_ / 8 / NTHR_) : (BN_ * KC / NTHR_);
    constexpr int KSN    = BK_ / 16;

    extern __shared__ __half sm[];
    int j = 0;
    #pragma unroll
    for (int t = 1; t < 4; t++)
        if (t < P.njobs && (int)blockIdx.x >= P.blk0[t]) j = t;
    const int rel = blockIdx.x - P.blk0[j];
    const int bx = rel % P.gx[j], by = rel / P.gx[j];

    const __half* __restrict__ Ah = P.Ah[j];
    const __half* __restrict__ Al = P.Al[j];
    const __half* __restrict__ Bh = P.Bh[j];
    const __half* __restrict__ Bl = P.Bl[j];
    const int N = P.N[j], K = P.K[j], Kld = P.Kld[j], Bld = P.Bld[j];
    const int koff = P.koff[j];
    const int tm = P.tm[j], mode = P.mode[j];

    const int tid  = threadIdx.x;
    const int lane = tid & 31, wid = tid >> 5;
    const int warp_m = wid & 3, warp_n = wid >> 2;       // warp tile 32x64
    const int bm0 = by * 128, bn0 = bx * BN_;
    const uint32_t su = smem_u32(sm);

    float acc[2][8][4];
    #pragma unroll
    for (int i = 0; i < 2; i++)
        #pragma unroll
        for (int q = 0; q < 8; q++)
            #pragma unroll
            for (int k = 0; k < 4; k++) acc[i][q][k] = 0.0f;

#define LOAD_STAGE(s, kt) do {                                                \
    const uint32_t sbase_ = su + (uint32_t)(s) * STAGE;                       \
    const size_t col0_ = (size_t)koff + (size_t)(kt) * BK_;                   \
    _Pragma("unroll")                                                         \
    for (int it_ = 0; it_ < A_IT; it_++) {                                    \
        const int c_ = tid + it_ * NTHR_;                                     \
        const int row_ = c_ / KC;                                             \
        const int kc_ = (c_ % KC) * 8;                                        \
        const uint32_t off_ = (uint32_t)(row_ * TS + kc_) * 2;                \
        const size_t ga_ = (size_t)(bm0 + row_) * Kld + col0_ + kc_;          \
        cp_async16(sbase_ + off_, Ah + ga_);                                  \
        if (tm & 2) cp_async16(sbase_ + TILE_A + off_, Al + ga_);             \
    }                                                                         \
    if (TRB_) {                                                               \
        _Pragma("unroll")                                                     \
        for (int it_ = 0; it_ < B_IT; it_++) {                                \
            const int c_ = tid + it_ * NTHR_;                                 \
            const int row_ = c_ / (BN_ / 8);                                  \
            const int nc_ = (c_ % (BN_ / 8)) * 8;                             \
            const uint32_t off_ = (uint32_t)(row_ * TSB + nc_) * 2;           \
            const size_t gb_ = (col0_ + row_) * (size_t)Bld + bn0 + nc_;      \
            cp_async16(sbase_ + 2 * TILE_A + off_, Bh + gb_);                 \
            if (tm & 1) cp_async16(sbase_ + 2 * TILE_A + TILE_B + off_,       \
                                   Bl + gb_);                                 \
        }                                                                     \
    } else {                                                                  \
        _Pragma("unroll")                                                     \
        for (int it_ = 0; it_ < B_IT; it_++) {                                \
            const int c_ = tid + it_ * NTHR_;                                 \
            const int row_ = c_ / KC;                                         \
            const int kc_ = (c_ % KC) * 8;                                    \
            const uint32_t off_ = (uint32_t)(row_ * TS + kc_) * 2;            \
            const size_t gb_ = (size_t)(bn0 + row_) * Kld + col0_ + kc_;      \
            cp_async16(sbase_ + 2 * TILE_A + off_, Bh + gb_);                 \
            if (tm & 1) cp_async16(sbase_ + 2 * TILE_A + TILE_B + off_,       \
                                   Bl + gb_);                                 \
        }                                                                     \
    }                                                                         \
    cp_commit();                                                              \
} while (0)

    const int NT = K / BK_;
    LOAD_STAGE(0, 0);

    for (int kt = 0; kt < NT; kt++) {
        if (kt + 1 < NT) {
            LOAD_STAGE((kt + 1) & 1, kt + 1);
            asm volatile("cp.async.wait_group 1;" ::: "memory");
        } else {
            asm volatile("cp.async.wait_group 0;" ::: "memory");
        }
        __syncthreads();

        const uint32_t sbase = su + (uint32_t)(kt & 1) * STAGE;
        #pragma unroll
        for (int ks = 0; ks < KSN; ks++) {
            uint32_t ah[2][4], al[2][4];
            #pragma unroll
            for (int i = 0; i < 2; i++) {
                const int r   = warp_m * 32 + i * 16 + (lane & 15);
                const int col = ks * 16 + (lane >> 4) * 8;
                const uint32_t ad = sbase + (uint32_t)(r * TS + col) * 2;
                ldsm4(ad, ah[i][0], ah[i][1], ah[i][2], ah[i][3]);
                if (tm & 2)
                    ldsm4(ad + TILE_A, al[i][0], al[i][1], al[i][2], al[i][3]);
            }
            if (TRB_) {
                const uint32_t brow = sbase + 2 * TILE_A +
                    (uint32_t)((ks * 16 + (lane & 15)) * TSB + ((lane >> 4) << 3)) * 2;
                #pragma unroll
                for (int p = 0; p < 4; p++) {
                    const uint32_t bd = brow + (uint32_t)(warp_n * 64 + p * 16) * 2;
                    uint32_t b0, b1, b2, b3;
                    ldsm4_t(bd, b0, b1, b2, b3);
                    #pragma unroll
                    for (int i = 0; i < 2; i++) {
                        hmma(acc[i][2*p],   ah[i], b0, b1);
                        hmma(acc[i][2*p+1], ah[i], b2, b3);
                    }
                    if (tm & 2) {
                        #pragma unroll
                        for (int i = 0; i < 2; i++) {
                            hmma(acc[i][2*p],   al[i], b0, b1);
                            hmma(acc[i][2*p+1], al[i], b2, b3);
                        }
                    }
                    if (tm & 1) {
                        uint32_t c0, c1, c2, c3;
                        ldsm4_t(bd + TILE_B, c0, c1, c2, c3);
                        #pragma unroll
                        for (int i = 0; i < 2; i++) {
                            hmma(acc[i][2*p],   ah[i], c0, c1);
                            hmma(acc[i][2*p+1], ah[i], c2, c3);
                        }
                    }
                }
            } else {
                const int g  = lane >> 3, i8 = lane & 7;
                const int n0r = warp_n * 64 + ((g >> 1) << 3) + i8;
                const int bcol = ks * 16 + (g & 1) * 8;
                const uint32_t bd0 = sbase + 2 * TILE_A +
                                     (uint32_t)(n0r * TS + bcol) * 2;
                #pragma unroll
                for (int p = 0; p < 4; p++) {
                    const uint32_t bd = bd0 + (uint32_t)(p * 16 * TS * 2);
                    uint32_t b0, b1, b2, b3;
                    ldsm4(bd, b0, b1, b2, b3);
                    uint32_t c0, c1, c2, c3;
                    if (tm & 1)
                        ldsm4(bd + TILE_B, c0, c1, c2, c3);
                    #pragma unroll
                    for (int i = 0; i < 2; i++) {
                        hmma(acc[i][2*p],   ah[i], b0, b1);
                        hmma(acc[i][2*p+1], ah[i], b2, b3);
                    }
                    if (tm & 2) {
                        #pragma unroll
                        for (int i = 0; i < 2; i++) {
                            hmma(acc[i][2*p],   al[i], b0, b1);
                            hmma(acc[i][2*p+1], al[i], b2, b3);
                        }
                    }
                    if (tm & 1) {
                        #pragma unroll
                        for (int i = 0; i < 2; i++) {
                            hmma(acc[i][2*p],   ah[i], c0, c1);
                            hmma(acc[i][2*p+1], ah[i], c2, c3);
                        }
                    }
                }
            }
        }
        __syncthreads();
    }
#undef LOAD_STAGE

    // ---- epilogue ----
    const int tq = lane >> 2, tr = lane & 3;
    const float gam = (mode == 3) ? P.gpt[0] : 0.0f;
    #pragma unroll
    for (int i = 0; i < 2; i++) {
        #pragma unroll
        for (int h2 = 0; h2 < 2; h2++) {
            const int row = bm0 + warp_m * 32 + i * 16 + tq + h2 * 8;
            const float bm_ = (mode <= 1) ? P.bias[j][row] : 0.0f;
            #pragma unroll
            for (int q = 0; q < 8; q++) {
                const int col = bn0 + warp_n * 64 + q * 8 + tr * 2;
                float v0 = acc[i][q][h2 * 2 + 0];
                float v1 = acc[i][q][h2 * 2 + 1];
                const size_t idx = (size_t)row * N + col;
                if (mode == 0) {
                    v0 += bm_; v1 += bm_;
                    const __half h0 = __float2half_rn(v0);
                    const __half h1 = __float2half_rn(v1);
                    *reinterpret_cast<__half2*>(P.Ch[j] + idx) = __halves2half2(h0, h1);
                    *reinterpret_cast<__half2*>(P.Cl[j] + idx) =
                        __halves2half2(__float2half_rn(v0 - __half2float(h0)),
                                       __float2half_rn(v1 - __half2float(h1)));
                } else if (mode == 1) {
                    v0 += bm_; v1 += bm_;
                    *reinterpret_cast<__half2*>(P.Ch[j] + idx) =
                        __halves2half2(__float2half_rn(v0), __float2half_rn(v1));
                } else if (mode == 2) {
                    *reinterpret_cast<float2*>(P.Cf[j] + idx) = make_float2(v0, v1);
                } else {
                    const float2 a2 = *reinterpret_cast<const float2*>(P.xf + idx);
                    const float2 b2 = *reinterpret_cast<const float2*>(P.xl + idx);
                    *reinterpret_cast<float2*>(P.Cf[j] + idx) =
                        make_float2(gam * v0 + 0.5f * (a2.x + b2.x),
                                    gam * v1 + 0.5f * (a2.y + b2.y));
                }
            }
        }
    }
}

#define SMEM_CONV  75776    // <128,32,256,2,1>  (2-stage, 2 CTA/SM)
#define SMEM_LOGIT 221184   // <256,64,512,1,0>
#define SMEM_FIN   208896   // <256,64,512,1,1>

// ---------------- vectorized merged splits (8 elems/thread) -----------------
struct S8 { const float* x[8]; __half* h[8]; __half* l[8]; int end[8]; };
__global__ __launch_bounds__(256)
void split8_kernel(S8 S)
{
    const int i8 = (blockIdx.x * 256 + threadIdx.x) * 8;
    if (i8 >= S.end[7]) return;
    int j = 0;
    #pragma unroll
    for (int t = 1; t < 8; t++) if (i8 >= S.end[t - 1]) j = t;
    const int base = (j == 0) ? 0 : S.end[j - 1];
    const int k = i8 - base;
    const float4 v0 = *reinterpret_cast<const float4*>(S.x[j] + k);
    const float4 v1 = *reinterpret_cast<const float4*>(S.x[j] + k + 4);
    const float f[8] = {v0.x, v0.y, v0.z, v0.w, v1.x, v1.y, v1.z, v1.w};
    uint32_t ph[4], pl[4];
    #pragma unroll
    for (int t = 0; t < 4; t++) {
        const __half ha = __float2half_rn(f[2*t]), hb = __float2half_rn(f[2*t+1]);
        const __half2 hp = __halves2half2(ha, hb);
        ph[t] = *reinterpret_cast<const uint32_t*>(&hp);
        const __half2 lp = __halves2half2(
            __float2half_rn(f[2*t]   - __half2float(ha)),
            __float2half_rn(f[2*t+1] - __half2float(hb)));
        pl[t] = *reinterpret_cast<const uint32_t*>(&lp);
    }
    *reinterpret_cast<uint4*>(S.h[j] + k) = make_uint4(ph[0], ph[1], ph[2], ph[3]);
    if (S.l[j])
        *reinterpret_cast<uint4*>(S.l[j] + k) = make_uint4(pl[0], pl[1], pl[2], pl[3]);
}

// ---------------- fused dual softmax (shuffle reductions) -------------------
__device__ __forceinline__ float blk_red(float v, bool mx, float* red,
                                         int tid)
{
    #pragma unroll
    for (int o = 16; o > 0; o >>= 1) {
        const float t = __shfl_xor_sync(0xFFFFFFFFu, v, o);
        v = mx ? fmaxf(v, t) : (v + t);
    }
    if ((tid & 31) == 0) red[tid >> 5] = v;
    __syncthreads();
    float r = red[0];
    #pragma unroll
    for (int w = 1; w < 8; w++) r = mx ? fmaxf(r, red[w]) : (r + red[w]);
    __syncthreads();
    return r;
}

__global__ __launch_bounds__(256)
void softmax_sum_kernel(const float* __restrict__ LF0, const float* __restrict__ LF1,
                        const float* __restrict__ LL0, const float* __restrict__ LL1,
                        __half* __restrict__ Sh)
{
    const int row = blockIdx.x;
    const int tid = threadIdx.x;
    __shared__ float red[8];

    const size_t rb = (size_t)row * 1024 + tid * 4;
    const float4 f0 = *reinterpret_cast<const float4*>(LF0 + rb);
    const float4 f1 = *reinterpret_cast<const float4*>(LF1 + rb);
    const float4 l0 = *reinterpret_cast<const float4*>(LL0 + rb);
    const float4 l1 = *reinterpret_cast<const float4*>(LL1 + rb);
    const float vf[4] = {f0.x + f1.x, f0.y + f1.y, f0.z + f1.z, f0.w + f1.w};
    const float vl[4] = {l0.x + l1.x, l0.y + l1.y, l0.z + l1.z, l0.w + l1.w};

    const float Mf = blk_red(fmaxf(fmaxf(vf[0], vf[1]), fmaxf(vf[2], vf[3])),
                             true, red, tid);
    float ef[4], sf = 0.0f;
    #pragma unroll
    for (int k = 0; k < 4; k++) { ef[k] = expf(vf[k] - Mf); sf += ef[k]; }
    const float Sf = blk_red(sf, false, red, tid);

    const float Ml = blk_red(fmaxf(fmaxf(vl[0], vl[1]), fmaxf(vl[2], vl[3])),
                             true, red, tid);
    float el[4], sl = 0.0f;
    #pragma unroll
    for (int k = 0; k < 4; k++) { el[k] = expf(vl[k] - Ml); sl += el[k]; }
    const float Sl_ = blk_red(sl, false, red, tid);

    const float invf = 1.0f / Sf, invl = 1.0f / Sl_;
    uint32_t pk[2];
    #pragma unroll
    for (int t = 0; t < 2; t++) {
        const __half2 hp = __halves2half2(
            __float2half_rn(ef[2*t]   * invf + el[2*t]   * invl),
            __float2half_rn(ef[2*t+1] * invf + el[2*t+1] * invl));
        pk[t] = *reinterpret_cast<const uint32_t*>(&hp);
    }
    *reinterpret_cast<uint2*>(Sh + rb) = make_uint2(pk[0], pk[1]);
}

// ---------------------------------------------------------------------------
extern "C" void kernel_launch(void* const* d_in, const int* in_sizes, int n_in,
                              void* d_out, int out_size)
{
    (void)in_sizes; (void)n_in; (void)out_size;
    const float* x_f   = (const float*)d_in[0];
    const float* x_m   = (const float*)d_in[1];
    const float* x_l   = (const float*)d_in[2];
    const float* Wq    = (const float*)d_in[3];
    const float* bq    = (const float*)d_in[4];
    const float* Wk1   = (const float*)d_in[5];
    const float* bk1   = (const float*)d_in[6];
    const float* Wk2   = (const float*)d_in[7];
    const float* bk2   = (const float*)d_in[8];
    const float* Wv    = (const float*)d_in[9];
    const float* bv    = (const float*)d_in[10];
    const float* gamma = (const float*)d_in[11];
    float* out = (float*)d_out;

    __half *xm_h, *xm_l, *xf_h, *xf_l, *xl_h, *xl_l;
    __half *wq_h, *wq_l, *wk1_h, *wk1_l, *wk2_h, *wk2_l, *wv_h;
    __half *q_h, *q_l, *kf_h, *kf_l, *kl_h, *kl_l, *v_h, *s_h;
    float *lf0, *lf1, *ll0, *ll1;
    cudaGetSymbolAddress((void**)&xm_h, g_xm_h); cudaGetSymbolAddress((void**)&xm_l, g_xm_l);
    cudaGetSymbolAddress((void**)&xf_h, g_xf_h); cudaGetSymbolAddress((void**)&xf_l, g_xf_l);
    cudaGetSymbolAddress((void**)&xl_h, g_xl_h); cudaGetSymbolAddress((void**)&xl_l, g_xl_l);
    cudaGetSymbolAddress((void**)&wq_h,  g_Wq_h);  cudaGetSymbolAddress((void**)&wq_l,  g_Wq_l);
    cudaGetSymbolAddress((void**)&wk1_h, g_Wk1_h); cudaGetSymbolAddress((void**)&wk1_l, g_Wk1_l);
    cudaGetSymbolAddress((void**)&wk2_h, g_Wk2_h); cudaGetSymbolAddress((void**)&wk2_l, g_Wk2_l);
    cudaGetSymbolAddress((void**)&wv_h,  g_Wv_h);
    cudaGetSymbolAddress((void**)&q_h,  g_q_h);  cudaGetSymbolAddress((void**)&q_l,  g_q_l);
    cudaGetSymbolAddress((void**)&kf_h, g_kf_h); cudaGetSymbolAddress((void**)&kf_l, g_kf_l);
    cudaGetSymbolAddress((void**)&kl_h, g_kl_h); cudaGetSymbolAddress((void**)&kl_l, g_kl_l);
    cudaGetSymbolAddress((void**)&v_h, g_v_h);
    cudaGetSymbolAddress((void**)&s_h, g_S_h);
    cudaGetSymbolAddress((void**)&lf0, g_lf0);   cudaGetSymbolAddress((void**)&lf1, g_lf1);
    cudaGetSymbolAddress((void**)&ll0, g_ll0);   cudaGetSymbolAddress((void**)&ll1, g_ll1);

    cudaFuncSetAttribute(mma_gemm<128, 32, 256, 2, 1>,
                         cudaFuncAttributeMaxDynamicSharedMemorySize, SMEM_CONV);
    cudaFuncSetAttribute(mma_gemm<256, 64, 512, 1, 0>,
                         cudaFuncAttributeMaxDynamicSharedMemorySize, SMEM_LOGIT);
    cudaFuncSetAttribute(mma_gemm<256, 64, 512, 1, 1>,
                         cudaFuncAttributeMaxDynamicSharedMemorySize, SMEM_FIN);

    // 1) all splits in one launch: 4 weights + 3 activations
    {
        S8 S = {};
        S.x[0] = Wq;  S.h[0] = wq_h;  S.l[0] = wq_l;
        S.x[1] = Wk1; S.h[1] = wk1_h; S.l[1] = wk1_l;
        S.x[2] = Wk2; S.h[2] = wk2_h; S.l[2] = wk2_l;
        S.x[3] = Wv;  S.h[3] = wv_h;  S.l[3] = nullptr;
        S.x[4] = x_m; S.h[4] = xm_h;  S.l[4] = xm_l;
        S.x[5] = x_f; S.h[5] = xf_h;  S.l[5] = xf_l;
        S.x[6] = x_l; S.h[6] = xl_h;  S.l[6] = xl_l;
        S.x[7] = Wq;  S.h[7] = wq_h;  S.l[7] = nullptr;
        const int nw = C_HALF * C_FULL, nx = C_FULL * HW;
        S.end[0] = nw; S.end[1] = 2 * nw; S.end[2] = 3 * nw;
        S.end[3] = 3 * nw + C_FULL * C_FULL;
        S.end[4] = S.end[3] + nx; S.end[5] = S.end[4] + nx;
        S.end[6] = S.end[5] + nx; S.end[7] = S.end[6];
        split8_kernel<<<(S.end[6] / 8 + 255) / 256, 256>>>(S);
    }

    // 2) all 4 conv GEMMs, narrow NN core, 2-stage (640 CTAs, 2/SM)
    {
        Jobs P = {};
        const __half* Ahs[3] = {wq_h, wk1_h, wk2_h};
        const __half* Als[3] = {wq_l, wk1_l, wk2_l};
        const __half* Bhs[3] = {xm_h, xf_h, xl_h};
        const __half* Bls[3] = {xm_l, xf_l, xl_l};
        __half* Chs[3] = {q_h, kf_h, kl_h};
        __half* Cls[3] = {q_l, kf_l, kl_l};
        const float* bs[3] = {bq, bk1, bk2};
        for (int t = 0; t < 3; t++) {
            P.Ah[t] = Ahs[t]; P.Al[t] = Als[t]; P.Bh[t] = Bhs[t]; P.Bl[t] = Bls[t];
            P.Ch[t] = Chs[t]; P.Cl[t] = Cls[t]; P.bias[t] = bs[t];
            P.N[t] = HW; P.K[t] = C_FULL; P.Kld[t] = C_FULL; P.Bld[t] = HW;
            P.koff[t] = 0;
            P.gx[t] = HW / 128;                              // 32
            P.tm[t] = 3; P.mode[t] = 0; P.blk0[t] = t * 128;
        }
        P.Ah[3] = wv_h; P.Al[3] = nullptr; P.Bh[3] = xm_h; P.Bl[3] = xm_l;
        P.Ch[3] = v_h; P.bias[3] = bv;
        P.N[3] = HW; P.K[3] = C_FULL; P.Kld[3] = C_FULL; P.Bld[3] = HW;
        P.koff[3] = 0;
        P.gx[3] = HW / 128;                                  // 32
        P.tm[3] = 1; P.mode[3] = 1; P.blk0[3] = 384;
        P.njobs = 4;
        mma_gemm<128, 32, 256, 2, 1><<<640, 256, SMEM_CONV>>>(P);
    }

    // 3) logits, wide NT core, split-K=2 (4 jobs x 32 CTAs = 128)
    {
        Jobs P = {};
        const __half* As[4] = {kf_h, kf_h, kl_h, kl_h};
        const __half* Als[4] = {kf_l, kf_l, kl_l, kl_l};
        float* Cs[4] = {lf0, lf1, ll0, ll1};
        const int kos[4] = {0, 1024, 0, 1024};
        for (int t = 0; t < 4; t++) {
            P.Ah[t] = As[t]; P.Al[t] = Als[t]; P.Bh[t] = q_h; P.Bl[t] = q_l;
            P.Cf[t] = Cs[t];
            P.N[t] = C_FULL; P.K[t] = 1024; P.Kld[t] = KLOG; P.Bld[t] = KLOG;
            P.koff[t] = kos[t];
            P.gx[t] = C_FULL / 256;                          // 4
            P.tm[t] = 3; P.mode[t] = 2; P.blk0[t] = t * 32;
        }
        P.njobs = 4;
        mma_gemm<256, 64, 512, 1, 0><<<128, 512, SMEM_LOGIT>>>(P);
    }

    // 4) S = softmax(lf0+lf1) + softmax(ll0+ll1)  (hi only)
    softmax_sum_kernel<<<C_FULL, 256>>>(lf0, lf1, ll0, ll1, s_h);

    // 5) out = gamma * (S_h @ v_h) + 0.5*(x_f + x_l)  (wide NN, 1-term)
    {
        Jobs P = {};
        P.Ah[0] = s_h; P.Al[0] = nullptr; P.Bh[0] = v_h; P.Bl[0] = nullptr;
        P.Cf[0] = out; P.xf = x_f; P.xl = x_l; P.gpt = gamma;
        P.N[0] = HW; P.K[0] = C_FULL; P.Kld[0] = C_FULL; P.Bld[0] = HW;
        P.koff[0] = 0;
        P.gx[0] = HW / 256;                                  // 16
        P.tm[0] = 0; P.mode[0] = 3; P.blk0[0] = 0;
        P.njobs = 1;
        mma_gemm<256, 64, 512, 1, 1><<<128, 512, SMEM_FIN>>>(P);
    }
}